// round 1
// baseline (speedup 1.0000x reference)
#include <cuda_runtime.h>
#include <math.h>

#define NB   8
#define NC   256
#define LNC  19
#define HH   64
#define WW   64
#define SL   512
#define PIX  (HH*WW)
#define PD   68   // padded spatial (64 + 2*2)

// ---------------- scratch (device globals: allocation-free) ----------------
static __device__ float g_mean[NB*NC];
static __device__ float g_rstd[NB*NC];
static __device__ int   g_labp[NB*PD*PD];          // padded label map, -1 = none/border
static __device__ float g_mu[NB*LNC*SL];           // relu(style @ fc_w + fc_b)
static __device__ float g_WshT[475*512];           // [j*25+i][k]
static __device__ float g_WspT[12800*512];         // [c*25+d][o2]  (spade gamma|beta)
static __device__ float g_WgbT[12800*512];         // [d*512+e][o2] (avg gamma|beta)
static __device__ float g_G[NB*LNC*25*512];        // [(b*19+j)*25+d][o2]
static __device__ float g_gavg[NB*PIX*512];        // [b*PIX+p][o2] gamma_avg|beta_avg (no bias)
static __device__ float g_actv1[NB*PIX*512];       // [b*PIX+p][k]
static __device__ float g_apad[NB*512*PD*PD];      // [b][k][PD][PD] zero-padded actv
static __device__ float g_gsp[NB*512*PIX];         // [b][o2][h][w] gamma_spade|beta_spade (with bias)

// ---------------- instance norm stats ----------------
__global__ void k_stats(const float* __restrict__ x) {
    int bc = blockIdx.x;
    const float* p = x + (size_t)bc * PIX;
    float s = 0.f, ss = 0.f;
    for (int i = threadIdx.x; i < PIX; i += 256) { float v = p[i]; s += v; ss += v * v; }
    __shared__ float sh[512];
    sh[threadIdx.x] = s; sh[256 + threadIdx.x] = ss; __syncthreads();
    for (int off = 128; off > 0; off >>= 1) {
        if (threadIdx.x < off) { sh[threadIdx.x] += sh[threadIdx.x + off]; sh[256 + threadIdx.x] += sh[256 + threadIdx.x + off]; }
        __syncthreads();
    }
    if (threadIdx.x == 0) {
        float m = sh[0] / (float)PIX;
        float v = sh[256] / (float)PIX - m * m;
        g_mean[bc] = m; g_rstd[bc] = rsqrtf(v + 1e-5f);
    }
}

// ---------------- padded label map ----------------
__global__ void k_labels(const float* __restrict__ segmap) {
    int idx = blockIdx.x * 256 + threadIdx.x;
    if (idx >= NB * PD * PD) return;
    int b = idx / (PD * PD), rem = idx % (PD * PD);
    int y = rem / PD, xx = rem % PD;
    int lab = -1;
    if (y >= 2 && y < 66 && xx >= 2 && xx < 66) {
        int h = y - 2, w = xx - 2;
        for (int j = LNC - 1; j >= 0; j--) {
            if (segmap[((b * LNC + j) * HH + h) * WW + w] > 0.f) { lab = j; break; }
        }
    }
    g_labp[idx] = lab;
}

// ---------------- mu = relu(style @ fc_w + fc_b) ----------------
__global__ void k_mu(const float* __restrict__ style, const float* __restrict__ fc_w,
                     const float* __restrict__ fc_b) {
    int bj = blockIdx.x;           // 0..151
    int b = bj / LNC, j = bj % LNC;
    int tid = threadIdx.x, lane = tid & 31, wid = tid >> 5;
    __shared__ float sc[SL];
    for (int i = tid; i < SL; i += 256) sc[i] = style[(b * LNC + j) * SL + i];
    __syncthreads();
    for (int e = wid; e < SL; e += 8) {
        const float* row = fc_w + ((size_t)(j * SL + e)) * SL;
        float acc = 0.f;
        for (int d = lane; d < SL; d += 32) acc += sc[d] * row[d];
        for (int off = 16; off; off >>= 1) acc += __shfl_xor_sync(0xffffffffu, acc, off);
        if (lane == 0) {
            float v = acc + fc_b[j * SL + e];
            g_mu[(b * LNC + j) * SL + e] = fmaxf(v, 0.f);
        }
    }
}

// ---------------- generic tiled transpose: out[rowmap(n)*stride + colOff + m] = in[m][n] ----------------
__global__ void k_transpose(const float* __restrict__ in, float* __restrict__ out,
                            int M, int N, int outStride, int colOff, int mode) {
    __shared__ float t[32][33];
    int n0 = blockIdx.x * 32, m0 = blockIdx.y * 32;
    int tx = threadIdx.x, ty = threadIdx.y;
    for (int r = ty; r < 32; r += 8) {
        int m = m0 + r, n = n0 + tx;
        t[r][tx] = (m < M && n < N) ? in[(size_t)m * N + n] : 0.f;
    }
    __syncthreads();
    for (int r = ty; r < 32; r += 8) {
        int n = n0 + r, m = m0 + tx;
        if (n < N && m < M) {
            int orow = (mode == 1) ? (n % 25) * 512 + (n / 25) : n;
            out[(size_t)orow * outStride + colOff + m] = t[tx][r];
        }
    }
}

// ---------------- G[b,j,d,o2] = sum_e WgbT[d,e,o2] * mu[b,j,e] ----------------
__global__ void k_G() {
    __shared__ float mus[4 * SL];
    int bj0 = blockIdx.x * 4;
    int off = blockIdx.y;            // 0..24
    int tid = threadIdx.x;
    for (int i = tid; i < 4 * SL; i += 256) mus[i] = g_mu[bj0 * SL + i];
    __syncthreads();
    float a0g = 0, a0b = 0, a1g = 0, a1b = 0, a2g = 0, a2b = 0, a3g = 0, a3b = 0;
    const float* wrow = g_WgbT + (size_t)off * 512 * 512;
    for (int e = 0; e < 512; e++) {
        float wa = wrow[e * 512 + tid];
        float wb = wrow[e * 512 + tid + 256];
        float m0 = mus[e], m1 = mus[512 + e], m2 = mus[1024 + e], m3 = mus[1536 + e];
        a0g += m0 * wa; a0b += m0 * wb;
        a1g += m1 * wa; a1b += m1 * wb;
        a2g += m2 * wa; a2b += m2 * wb;
        a3g += m3 * wa; a3b += m3 * wb;
    }
    float* o0 = g_G + ((size_t)((bj0 + 0) * 25 + off)) * 512;
    float* o1 = g_G + ((size_t)((bj0 + 1) * 25 + off)) * 512;
    float* o2 = g_G + ((size_t)((bj0 + 2) * 25 + off)) * 512;
    float* o3 = g_G + ((size_t)((bj0 + 3) * 25 + off)) * 512;
    o0[tid] = a0g; o0[tid + 256] = a0b;
    o1[tid] = a1g; o1[tid + 256] = a1b;
    o2[tid] = a2g; o2[tid + 256] = a2b;
    o3[tid] = a3g; o3[tid + 256] = a3b;
}

// ---------------- gather: gavg[b,p,o2] = sum over 25 window offsets of G ----------------
__global__ void k_gather() {
    int bh = blockIdx.x;
    int b = bh >> 6, h = bh & 63;
    int tid = threadIdx.x;
    __shared__ int labw[5 * PD];
    for (int i = tid; i < 5 * PD; i += 256)
        labw[i] = g_labp[(b * PD + h + i / PD) * PD + (i % PD)];
    __syncthreads();
    for (int w = 0; w < WW; w++) {
        float a0 = 0.f, a1 = 0.f;
        #pragma unroll
        for (int i = 0; i < 25; i++) {
            int j = labw[(i / 5) * PD + w + (i % 5)];
            if (j >= 0) {
                const float* g = g_G + ((size_t)((b * LNC + j) * 25 + i)) * 512;
                a0 += g[tid]; a1 += g[tid + 256];
            }
        }
        float* o = g_gavg + ((size_t)(b * PIX + h * WW + w)) * 512;
        o[tid] = a0; o[tid + 256] = a1;
    }
}

// ---------------- actv[b,p,k] = relu(sh_b[k] + sum_i WshT[L*25+i][k]) ----------------
__global__ void k_actv(const float* __restrict__ sh_b) {
    int bh = blockIdx.x;
    int b = bh >> 6, h = bh & 63;
    int tid = threadIdx.x;
    __shared__ int labw[5 * PD];
    for (int i = tid; i < 5 * PD; i += 256)
        labw[i] = g_labp[(b * PD + h + i / PD) * PD + (i % PD)];
    __syncthreads();
    float bias0 = sh_b[tid], bias1 = sh_b[tid + 256];
    for (int w = 0; w < WW; w++) {
        float a0 = bias0, a1 = bias1;
        #pragma unroll
        for (int i = 0; i < 25; i++) {
            int j = labw[(i / 5) * PD + w + (i % 5)];
            if (j >= 0) {
                const float* g = g_WshT + ((size_t)(j * 25 + i)) * 512;
                a0 += g[tid]; a1 += g[tid + 256];
            }
        }
        float* o = g_actv1 + ((size_t)(b * PIX + h * WW + w)) * 512;
        o[tid] = fmaxf(a0, 0.f); o[tid + 256] = fmaxf(a1, 0.f);
    }
}

// ---------------- zero padded-activation borders ----------------
__global__ void k_border() {
    int idx = blockIdx.x * 256 + threadIdx.x;
    if (idx >= NB * 512 * PD * PD) return;
    int rem = idx % (PD * PD);
    int y = rem / PD, xx = rem % PD;
    if (y < 2 || y >= 66 || xx < 2 || xx >= 66) g_apad[idx] = 0.f;
}

// ---------------- transpose actv [b,p,k] -> apad [b,k,PD,PD] interior ----------------
__global__ void k_atrans() {
    __shared__ float t[32][33];
    int p0 = blockIdx.x * 32, k0 = blockIdx.y * 32, b = blockIdx.z;
    int tx = threadIdx.x, ty = threadIdx.y;
    for (int r = ty; r < 32; r += 8)
        t[r][tx] = g_actv1[((size_t)(b * PIX + p0 + r)) * 512 + k0 + tx];
    __syncthreads();
    for (int r = ty; r < 32; r += 8) {
        int k = k0 + r, p = p0 + tx;
        int h = p >> 6, w = p & 63;
        g_apad[((size_t)(b * 512 + k) * PD + (h + 2)) * PD + (w + 2)] = t[tx][r];
    }
}

// ---------------- fused spade conv: gsp[b,o2,h,w] (o2<256: gamma, else beta), biases included ----------------
__global__ void __launch_bounds__(256, 2)
k_conv(const float* __restrict__ sgb, const float* __restrict__ sbb) {
    __shared__ float Ws[2 * 25 * 128];   // [c][25][128]  25.6 KB
    __shared__ float As[2 * 6 * PD];     // [c][6][68]     3.3 KB
    int ob = blockIdx.x;                 // 0..3   (o2 tile of 128)
    int h0 = blockIdx.y * 2;             // 0..62  (2 output rows)
    int b  = blockIdx.z;
    int tid = threadIdx.x;
    int ty = tid >> 4;                   // 0..15  o-group (8 o2 each)
    int tx = tid & 15;
    int hh = tx >> 3;                    // 0/1 output row within tile
    int wg = tx & 7;                     // 0..7 px-group (8 px each)
    int o0 = ob * 128;
    int obase = o0 + (ty << 3);

    float acc[8][8];
    #pragma unroll
    for (int oi = 0; oi < 8; oi++) {
        int o2 = obase + oi;
        float bias = (o2 < 256) ? sgb[o2] : sbb[o2 - 256];
        #pragma unroll
        for (int pi = 0; pi < 8; pi++) acc[oi][pi] = bias;
    }

    for (int c0 = 0; c0 < 512; c0 += 2) {
        for (int idx = tid; idx < 6400; idx += 256) {
            int c = idx / 3200, rem = idx % 3200;
            Ws[idx] = g_WspT[((size_t)((c0 + c) * 25 + rem / 128)) * 512 + o0 + (rem & 127)];
        }
        for (int idx = tid; idx < 816; idx += 256) {
            int c = idx / 408, rem = idx % 408;
            As[idx] = g_apad[((size_t)(b * 512 + c0 + c) * PD + (h0 + rem / PD)) * PD + (rem % PD)];
        }
        __syncthreads();
        #pragma unroll
        for (int c = 0; c < 2; c++) {
            #pragma unroll 1
            for (int ky = 0; ky < 5; ky++) {
                const float4* ap = (const float4*)&As[(c * 6 + hh + ky) * PD + (wg << 3)];
                float4 A0 = ap[0], A1 = ap[1], A2 = ap[2];
                float a[12] = {A0.x, A0.y, A0.z, A0.w, A1.x, A1.y, A1.z, A1.w,
                               A2.x, A2.y, A2.z, A2.w};
                const float* wbase = &Ws[(c * 25 + ky * 5) * 128 + (ty << 3)];
                #pragma unroll
                for (int kx = 0; kx < 5; kx++) {
                    float4 W0 = *(const float4*)(wbase + kx * 128);
                    float4 W1 = *(const float4*)(wbase + kx * 128 + 4);
                    float wv[8] = {W0.x, W0.y, W0.z, W0.w, W1.x, W1.y, W1.z, W1.w};
                    #pragma unroll
                    for (int oi = 0; oi < 8; oi++)
                        #pragma unroll
                        for (int pi = 0; pi < 8; pi++)
                            acc[oi][pi] += wv[oi] * a[kx + pi];
                }
            }
        }
        __syncthreads();
    }

    int hout = h0 + hh;
    #pragma unroll
    for (int oi = 0; oi < 8; oi++) {
        float* op = &g_gsp[((size_t)(b * 512 + obase + oi) * HH + hout) * WW + (wg << 3)];
        float4 s0 = {acc[oi][0], acc[oi][1], acc[oi][2], acc[oi][3]};
        float4 s1 = {acc[oi][4], acc[oi][5], acc[oi][6], acc[oi][7]};
        ((float4*)op)[0] = s0; ((float4*)op)[1] = s1;
    }
}

// ---------------- final blend ----------------
__global__ void k_final(const float* __restrict__ x,
                        const float* __restrict__ cgb, const float* __restrict__ cbb,
                        const float* __restrict__ bg, const float* __restrict__ bb,
                        float* __restrict__ out) {
    int bh = blockIdx.x;
    int b = bh >> 6, h = bh & 63;
    int tid = threadIdx.x;
    int w = tid & 63, os = tid >> 6;     // os in [0,4)
    float ga = 1.f / (1.f + expf(-bg[0]));
    float ba = 1.f / (1.f + expf(-bb[0]));
    size_t gi = ((size_t)(b * PIX + h * WW + w)) * 512;
    for (int oc = 0; oc < NC; oc += 4) {
        int o = oc + os;
        float m = g_mean[b * NC + o], rs = g_rstd[b * NC + o];
        size_t xi = ((size_t)(b * NC + o) * HH + h) * WW + w;
        float nv = (x[xi] - m) * rs;
        float gs = g_gsp[((size_t)(b * 512 + o) * HH + h) * WW + w];
        float bs = g_gsp[((size_t)(b * 512 + o + 256) * HH + h) * WW + w];
        float gav = g_gavg[gi + o] + cgb[o];
        float bav = g_gavg[gi + 256 + o] + cbb[o];
        float gf = ga * gav + (1.f - ga) * gs;
        float bf = ba * bav + (1.f - ba) * bs;
        out[xi] = nv * (1.f + gf) + bf;
    }
}

// ---------------- launch ----------------
extern "C" void kernel_launch(void* const* d_in, const int* in_sizes, int n_in,
                              void* d_out, int out_size) {
    const float* x      = (const float*)d_in[0];
    const float* segmap = (const float*)d_in[1];
    const float* style  = (const float*)d_in[2];
    const float* fc_w   = (const float*)d_in[3];
    const float* fc_b   = (const float*)d_in[4];
    const float* cgw    = (const float*)d_in[5];
    const float* cgb    = (const float*)d_in[6];
    const float* cbw    = (const float*)d_in[7];
    const float* cbb    = (const float*)d_in[8];
    const float* ssw    = (const float*)d_in[9];
    const float* ssb    = (const float*)d_in[10];
    const float* sgw    = (const float*)d_in[11];
    const float* sgb    = (const float*)d_in[12];
    const float* sbw    = (const float*)d_in[13];
    const float* sbb    = (const float*)d_in[14];
    const float* bg     = (const float*)d_in[15];
    const float* bb     = (const float*)d_in[16];
    float* out = (float*)d_out;

    float* pWshT; cudaGetSymbolAddress((void**)&pWshT, g_WshT);
    float* pWspT; cudaGetSymbolAddress((void**)&pWspT, g_WspT);
    float* pWgbT; cudaGetSymbolAddress((void**)&pWgbT, g_WgbT);

    dim3 tb(32, 8);

    k_stats<<<NB * NC, 256>>>(x);
    k_labels<<<(NB * PD * PD + 255) / 256, 256>>>(segmap);
    k_mu<<<NB * LNC, 256>>>(style, fc_w, fc_b);

    // WshT: spade_shared_w [512][475] -> [475][512]
    k_transpose<<<dim3(15, 16), tb>>>(ssw, pWshT, 512, 475, 512, 0, 0);
    // WspT: spade gamma/beta weights [256][12800] -> [12800][512] (concat o2)
    k_transpose<<<dim3(400, 8), tb>>>(sgw, pWspT, 256, 12800, 512, 0, 0);
    k_transpose<<<dim3(400, 8), tb>>>(sbw, pWspT, 256, 12800, 512, 256, 0);
    // WgbT: avg gamma/beta weights [256][e*25+d] -> [d*512+e][512]
    k_transpose<<<dim3(400, 8), tb>>>(cgw, pWgbT, 256, 12800, 512, 0, 1);
    k_transpose<<<dim3(400, 8), tb>>>(cbw, pWgbT, 256, 12800, 512, 256, 1);

    k_G<<<dim3(38, 25), 256>>>();
    k_gather<<<NB * HH, 256>>>();
    k_actv<<<NB * HH, 256>>>(ssb);
    k_border<<<(NB * 512 * PD * PD + 255) / 256, 256>>>();
    k_atrans<<<dim3(PIX / 32, 512 / 32, NB), tb>>>();
    k_conv<<<dim3(4, 32, NB), 256>>>(sgb, sbb);
    k_final<<<NB * HH, 256>>>(x, cgb, cbb, bg, bb, out);
}

// round 2
// speedup vs baseline: 1.2125x; 1.2125x over previous
#include <cuda_runtime.h>
#include <math.h>

#define NB   8
#define NC   256
#define LNC  19
#define HH   64
#define WW   64
#define SL   512
#define PIX  (HH*WW)
#define PD   68   // padded spatial (64 + 2*2)

typedef unsigned long long ull;

// ---------------- scratch (device globals: allocation-free) ----------------
static __device__ float g_mean[NB*NC];
static __device__ float g_rstd[NB*NC];
static __device__ int   g_labp[NB*PD*PD];          // padded label map, -1 = none/border
static __device__ float g_mu[NB*LNC*SL];           // relu(style @ fc_w + fc_b)
static __device__ float g_WshT[475*512];           // [j*25+i][k]
static __device__ float g_WspT[12800*512];         // [c*25+d][o2]  (spade gamma|beta)
static __device__ float g_WgbT[12800*512];         // [d*512+e][o2] (avg gamma|beta)
static __device__ float g_G[NB*LNC*25*512];        // [(b*19+j)*25+d][o2]
static __device__ float g_gavg[NB*PIX*512];        // [b*PIX+p][o2] gamma_avg|beta_avg (no bias)
static __device__ float g_actv1[NB*PIX*512];       // [b*PIX+p][k]
static __device__ float g_apad[NB*512*PD*PD];      // [b][k][PD][PD] zero-padded actv
static __device__ float g_gsp[NB*512*PIX];         // [b][o2][h][w] gamma_spade|beta_spade (with bias)

// ---------------- packed f32x2 helpers ----------------
__device__ __forceinline__ void fma_f32x2(ull& d, ull a, ull b) {
    asm("fma.rn.f32x2 %0, %1, %2, %0;" : "+l"(d) : "l"(a), "l"(b));
}
__device__ __forceinline__ ull pack_dup(float x) {
    ull r;
    asm("mov.b64 %0, {%1, %1};" : "=l"(r) : "f"(x));
    return r;
}
__device__ __forceinline__ ull pack2(float lo, float hi) {
    ull r;
    asm("mov.b64 %0, {%1, %2};" : "=l"(r) : "f"(lo), "f"(hi));
    return r;
}
__device__ __forceinline__ void unpack2(ull v, float& lo, float& hi) {
    asm("mov.b64 {%0, %1}, %2;" : "=f"(lo), "=f"(hi) : "l"(v));
}

// ---------------- instance norm stats ----------------
__global__ void k_stats(const float* __restrict__ x) {
    int bc = blockIdx.x;
    const float* p = x + (size_t)bc * PIX;
    float s = 0.f, ss = 0.f;
    for (int i = threadIdx.x; i < PIX; i += 256) { float v = p[i]; s += v; ss += v * v; }
    __shared__ float sh[512];
    sh[threadIdx.x] = s; sh[256 + threadIdx.x] = ss; __syncthreads();
    for (int off = 128; off > 0; off >>= 1) {
        if (threadIdx.x < off) { sh[threadIdx.x] += sh[threadIdx.x + off]; sh[256 + threadIdx.x] += sh[256 + threadIdx.x + off]; }
        __syncthreads();
    }
    if (threadIdx.x == 0) {
        float m = sh[0] / (float)PIX;
        float v = sh[256] / (float)PIX - m * m;
        g_mean[bc] = m; g_rstd[bc] = rsqrtf(v + 1e-5f);
    }
}

// ---------------- padded label map ----------------
__global__ void k_labels(const float* __restrict__ segmap) {
    int idx = blockIdx.x * 256 + threadIdx.x;
    if (idx >= NB * PD * PD) return;
    int b = idx / (PD * PD), rem = idx % (PD * PD);
    int y = rem / PD, xx = rem % PD;
    int lab = -1;
    if (y >= 2 && y < 66 && xx >= 2 && xx < 66) {
        int h = y - 2, w = xx - 2;
        for (int j = LNC - 1; j >= 0; j--) {
            if (segmap[((b * LNC + j) * HH + h) * WW + w] > 0.f) { lab = j; break; }
        }
    }
    g_labp[idx] = lab;
}

// ---------------- mu = relu(style @ fc_w + fc_b) ----------------
__global__ void k_mu(const float* __restrict__ style, const float* __restrict__ fc_w,
                     const float* __restrict__ fc_b) {
    int bj = blockIdx.x;           // 0..151
    int b = bj / LNC, j = bj % LNC;
    int tid = threadIdx.x, lane = tid & 31, wid = tid >> 5;
    __shared__ float sc[SL];
    for (int i = tid; i < SL; i += 256) sc[i] = style[(b * LNC + j) * SL + i];
    __syncthreads();
    for (int e = wid; e < SL; e += 8) {
        const float* row = fc_w + ((size_t)(j * SL + e)) * SL;
        float acc = 0.f;
        for (int d = lane; d < SL; d += 32) acc += sc[d] * row[d];
        for (int off = 16; off; off >>= 1) acc += __shfl_xor_sync(0xffffffffu, acc, off);
        if (lane == 0) {
            float v = acc + fc_b[j * SL + e];
            g_mu[(b * LNC + j) * SL + e] = fmaxf(v, 0.f);
        }
    }
}

// ---------------- generic tiled transpose ----------------
__global__ void k_transpose(const float* __restrict__ in, float* __restrict__ out,
                            int M, int N, int outStride, int colOff, int mode) {
    __shared__ float t[32][33];
    int n0 = blockIdx.x * 32, m0 = blockIdx.y * 32;
    int tx = threadIdx.x, ty = threadIdx.y;
    for (int r = ty; r < 32; r += 8) {
        int m = m0 + r, n = n0 + tx;
        t[r][tx] = (m < M && n < N) ? in[(size_t)m * N + n] : 0.f;
    }
    __syncthreads();
    for (int r = ty; r < 32; r += 8) {
        int n = n0 + r, m = m0 + tx;
        if (n < N && m < M) {
            int orow = (mode == 1) ? (n % 25) * 512 + (n / 25) : n;
            out[(size_t)orow * outStride + colOff + m] = t[tx][r];
        }
    }
}

// ---------------- G[b,j,d,o2] = sum_e WgbT[d,e,o2] * mu[b,j,e] ----------------
__global__ void k_G() {
    __shared__ float mus[4 * SL];
    int bj0 = blockIdx.x * 4;
    int off = blockIdx.y;            // 0..24
    int tid = threadIdx.x;
    for (int i = tid; i < 4 * SL; i += 256) mus[i] = g_mu[bj0 * SL + i];
    __syncthreads();
    float a0g = 0, a0b = 0, a1g = 0, a1b = 0, a2g = 0, a2b = 0, a3g = 0, a3b = 0;
    const float* wrow = g_WgbT + (size_t)off * 512 * 512;
    for (int e = 0; e < 512; e++) {
        float wa = wrow[e * 512 + tid];
        float wb = wrow[e * 512 + tid + 256];
        float m0 = mus[e], m1 = mus[512 + e], m2 = mus[1024 + e], m3 = mus[1536 + e];
        a0g += m0 * wa; a0b += m0 * wb;
        a1g += m1 * wa; a1b += m1 * wb;
        a2g += m2 * wa; a2b += m2 * wb;
        a3g += m3 * wa; a3b += m3 * wb;
    }
    float* o0 = g_G + ((size_t)((bj0 + 0) * 25 + off)) * 512;
    float* o1 = g_G + ((size_t)((bj0 + 1) * 25 + off)) * 512;
    float* o2 = g_G + ((size_t)((bj0 + 2) * 25 + off)) * 512;
    float* o3 = g_G + ((size_t)((bj0 + 3) * 25 + off)) * 512;
    o0[tid] = a0g; o0[tid + 256] = a0b;
    o1[tid] = a1g; o1[tid + 256] = a1b;
    o2[tid] = a2g; o2[tid + 256] = a2b;
    o3[tid] = a3g; o3[tid + 256] = a3b;
}

// ---------------- gather: gavg[b,p,o2] = sum over 25 window offsets of G ----------------
__global__ void k_gather() {
    int bh = blockIdx.x;
    int b = bh >> 6, h = bh & 63;
    int tid = threadIdx.x;
    __shared__ int labw[5 * PD];
    for (int i = tid; i < 5 * PD; i += 256)
        labw[i] = g_labp[(b * PD + h + i / PD) * PD + (i % PD)];
    __syncthreads();
    for (int w = 0; w < WW; w++) {
        float a0 = 0.f, a1 = 0.f;
        #pragma unroll
        for (int i = 0; i < 25; i++) {
            int j = labw[(i / 5) * PD + w + (i % 5)];
            if (j >= 0) {
                const float* g = g_G + ((size_t)((b * LNC + j) * 25 + i)) * 512;
                a0 += g[tid]; a1 += g[tid + 256];
            }
        }
        float* o = g_gavg + ((size_t)(b * PIX + h * WW + w)) * 512;
        o[tid] = a0; o[tid + 256] = a1;
    }
}

// ---------------- actv[b,p,k] = relu(sh_b[k] + sum_i WshT[L*25+i][k]) ----------------
__global__ void k_actv(const float* __restrict__ sh_b) {
    int bh = blockIdx.x;
    int b = bh >> 6, h = bh & 63;
    int tid = threadIdx.x;
    __shared__ int labw[5 * PD];
    for (int i = tid; i < 5 * PD; i += 256)
        labw[i] = g_labp[(b * PD + h + i / PD) * PD + (i % PD)];
    __syncthreads();
    float bias0 = sh_b[tid], bias1 = sh_b[tid + 256];
    for (int w = 0; w < WW; w++) {
        float a0 = bias0, a1 = bias1;
        #pragma unroll
        for (int i = 0; i < 25; i++) {
            int j = labw[(i / 5) * PD + w + (i % 5)];
            if (j >= 0) {
                const float* g = g_WshT + ((size_t)(j * 25 + i)) * 512;
                a0 += g[tid]; a1 += g[tid + 256];
            }
        }
        float* o = g_actv1 + ((size_t)(b * PIX + h * WW + w)) * 512;
        o[tid] = fmaxf(a0, 0.f); o[tid + 256] = fmaxf(a1, 0.f);
    }
}

// ---------------- zero padded-activation borders ----------------
__global__ void k_border() {
    int idx = blockIdx.x * 256 + threadIdx.x;
    if (idx >= NB * 512 * PD * PD) return;
    int rem = idx % (PD * PD);
    int y = rem / PD, xx = rem % PD;
    if (y < 2 || y >= 66 || xx < 2 || xx >= 66) g_apad[idx] = 0.f;
}

// ---------------- transpose actv [b,p,k] -> apad [b,k,PD,PD] interior ----------------
__global__ void k_atrans() {
    __shared__ float t[32][33];
    int p0 = blockIdx.x * 32, k0 = blockIdx.y * 32, b = blockIdx.z;
    int tx = threadIdx.x, ty = threadIdx.y;
    for (int r = ty; r < 32; r += 8)
        t[r][tx] = g_actv1[((size_t)(b * PIX + p0 + r)) * 512 + k0 + tx];
    __syncthreads();
    for (int r = ty; r < 32; r += 8) {
        int k = k0 + r, p = p0 + tx;
        int h = p >> 6, w = p & 63;
        g_apad[((size_t)(b * 512 + k) * PD + (h + 2)) * PD + (w + 2)] = t[tx][r];
    }
}

// ---------------- fused spade conv (f32x2 packed FMA core) ----------------
// gsp[b,o2,h,w] (o2<256: gamma, else beta), biases included.
__global__ void __launch_bounds__(256, 2)
k_conv(const float* __restrict__ sgb, const float* __restrict__ sbb) {
    __shared__ float Ws[2 * 25 * 128];   // [c][25][128]  25.6 KB
    __shared__ float As[2 * 6 * PD];     // [c][6][68]     3.3 KB
    int ob = blockIdx.x;                 // 0..3   (o2 tile of 128)
    int h0 = blockIdx.y * 2;             // 0..62  (2 output rows)
    int b  = blockIdx.z;
    int tid = threadIdx.x;
    int ty = tid >> 4;                   // 0..15  o-group (8 o2 each)
    int tx = tid & 15;
    int hh = tx >> 3;                    // 0/1 output row within tile
    int wg = tx & 7;                     // 0..7 px-group (8 px each)
    int o0 = ob * 128;
    int obase = o0 + (ty << 3);

    // acc2[q][pi]: packed accumulators for channels (obase+2q, obase+2q+1), pixel pi
    ull acc2[4][8];
    #pragma unroll
    for (int q = 0; q < 4; q++) {
        int olo = obase + 2 * q;
        float blo = (olo < 256) ? sgb[olo] : sbb[olo - 256];
        float bhi = (olo + 1 < 256) ? sgb[olo + 1] : sbb[olo + 1 - 256];
        ull bp = pack2(blo, bhi);
        #pragma unroll
        for (int pi = 0; pi < 8; pi++) acc2[q][pi] = bp;
    }

    for (int c0 = 0; c0 < 512; c0 += 2) {
        for (int idx = tid; idx < 6400; idx += 256) {
            int c = idx / 3200, rem = idx % 3200;
            Ws[idx] = g_WspT[((size_t)((c0 + c) * 25 + rem / 128)) * 512 + o0 + (rem & 127)];
        }
        for (int idx = tid; idx < 816; idx += 256) {
            int c = idx / 408, rem = idx % 408;
            As[idx] = g_apad[((size_t)(b * 512 + c0 + c) * PD + (h0 + rem / PD)) * PD + (rem % PD)];
        }
        __syncthreads();
        #pragma unroll
        for (int c = 0; c < 2; c++) {
            #pragma unroll 1
            for (int ky = 0; ky < 5; ky++) {
                const float4* ap = (const float4*)&As[(c * 6 + hh + ky) * PD + (wg << 3)];
                float4 A0 = ap[0], A1 = ap[1], A2 = ap[2];
                ull ad[12];
                ad[0] = pack_dup(A0.x); ad[1] = pack_dup(A0.y);
                ad[2] = pack_dup(A0.z); ad[3] = pack_dup(A0.w);
                ad[4] = pack_dup(A1.x); ad[5] = pack_dup(A1.y);
                ad[6] = pack_dup(A1.z); ad[7] = pack_dup(A1.w);
                ad[8] = pack_dup(A2.x); ad[9] = pack_dup(A2.y);
                ad[10] = pack_dup(A2.z); ad[11] = pack_dup(A2.w);
                // thread's 8 weights per kx start at (c*25+ky*5+kx)*128 + ty*8
                const ulonglong2* wb =
                    (const ulonglong2*)&Ws[(c * 25 + ky * 5) * 128 + (ty << 3)];
                #pragma unroll
                for (int kx = 0; kx < 5; kx++) {
                    // 128 floats per kx row = 32 ulonglong2; thread slice = 2 ulonglong2
                    ulonglong2 wA = wb[kx * 32];      // q0, q1
                    ulonglong2 wB = wb[kx * 32 + 1];  // q2, q3
                    #pragma unroll
                    for (int pi = 0; pi < 8; pi++) {
                        ull a = ad[kx + pi];
                        fma_f32x2(acc2[0][pi], wA.x, a);
                        fma_f32x2(acc2[1][pi], wA.y, a);
                        fma_f32x2(acc2[2][pi], wB.x, a);
                        fma_f32x2(acc2[3][pi], wB.y, a);
                    }
                }
            }
        }
        __syncthreads();
    }

    int hout = h0 + hh;
    #pragma unroll
    for (int q = 0; q < 4; q++) {
        float lo[8], hi[8];
        #pragma unroll
        for (int pi = 0; pi < 8; pi++) unpack2(acc2[q][pi], lo[pi], hi[pi]);
        float* oplo = &g_gsp[((size_t)(b * 512 + obase + 2 * q) * HH + hout) * WW + (wg << 3)];
        float* ophi = &g_gsp[((size_t)(b * 512 + obase + 2 * q + 1) * HH + hout) * WW + (wg << 3)];
        float4 l0 = {lo[0], lo[1], lo[2], lo[3]}, l1 = {lo[4], lo[5], lo[6], lo[7]};
        float4 h0v = {hi[0], hi[1], hi[2], hi[3]}, h1v = {hi[4], hi[5], hi[6], hi[7]};
        ((float4*)oplo)[0] = l0; ((float4*)oplo)[1] = l1;
        ((float4*)ophi)[0] = h0v; ((float4*)ophi)[1] = h1v;
    }
}

// ---------------- final blend ----------------
__global__ void k_final(const float* __restrict__ x,
                        const float* __restrict__ cgb, const float* __restrict__ cbb,
                        const float* __restrict__ bg, const float* __restrict__ bb,
                        float* __restrict__ out) {
    int bh = blockIdx.x;
    int b = bh >> 6, h = bh & 63;
    int tid = threadIdx.x;
    int w = tid & 63, os = tid >> 6;     // os in [0,4)
    float ga = 1.f / (1.f + expf(-bg[0]));
    float ba = 1.f / (1.f + expf(-bb[0]));
    size_t gi = ((size_t)(b * PIX + h * WW + w)) * 512;
    for (int oc = 0; oc < NC; oc += 4) {
        int o = oc + os;
        float m = g_mean[b * NC + o], rs = g_rstd[b * NC + o];
        size_t xi = ((size_t)(b * NC + o) * HH + h) * WW + w;
        float nv = (x[xi] - m) * rs;
        float gs = g_gsp[((size_t)(b * 512 + o) * HH + h) * WW + w];
        float bs = g_gsp[((size_t)(b * 512 + o + 256) * HH + h) * WW + w];
        float gav = g_gavg[gi + o] + cgb[o];
        float bav = g_gavg[gi + 256 + o] + cbb[o];
        float gf = ga * gav + (1.f - ga) * gs;
        float bf = ba * bav + (1.f - ba) * bs;
        out[xi] = nv * (1.f + gf) + bf;
    }
}

// ---------------- launch ----------------
extern "C" void kernel_launch(void* const* d_in, const int* in_sizes, int n_in,
                              void* d_out, int out_size) {
    const float* x      = (const float*)d_in[0];
    const float* segmap = (const float*)d_in[1];
    const float* style  = (const float*)d_in[2];
    const float* fc_w   = (const float*)d_in[3];
    const float* fc_b   = (const float*)d_in[4];
    const float* cgw    = (const float*)d_in[5];
    const float* cgb    = (const float*)d_in[6];
    const float* cbw    = (const float*)d_in[7];
    const float* cbb    = (const float*)d_in[8];
    const float* ssw    = (const float*)d_in[9];
    const float* ssb    = (const float*)d_in[10];
    const float* sgw    = (const float*)d_in[11];
    const float* sgb    = (const float*)d_in[12];
    const float* sbw    = (const float*)d_in[13];
    const float* sbb    = (const float*)d_in[14];
    const float* bg     = (const float*)d_in[15];
    const float* bb     = (const float*)d_in[16];
    float* out = (float*)d_out;

    float* pWshT; cudaGetSymbolAddress((void**)&pWshT, g_WshT);
    float* pWspT; cudaGetSymbolAddress((void**)&pWspT, g_WspT);
    float* pWgbT; cudaGetSymbolAddress((void**)&pWgbT, g_WgbT);

    dim3 tb(32, 8);

    k_stats<<<NB * NC, 256>>>(x);
    k_labels<<<(NB * PD * PD + 255) / 256, 256>>>(segmap);
    k_mu<<<NB * LNC, 256>>>(style, fc_w, fc_b);

    k_transpose<<<dim3(15, 16), tb>>>(ssw, pWshT, 512, 475, 512, 0, 0);
    k_transpose<<<dim3(400, 8), tb>>>(sgw, pWspT, 256, 12800, 512, 0, 0);
    k_transpose<<<dim3(400, 8), tb>>>(sbw, pWspT, 256, 12800, 512, 256, 0);
    k_transpose<<<dim3(400, 8), tb>>>(cgw, pWgbT, 256, 12800, 512, 0, 1);
    k_transpose<<<dim3(400, 8), tb>>>(cbw, pWgbT, 256, 12800, 512, 256, 1);

    k_G<<<dim3(38, 25), 256>>>();
    k_gather<<<NB * HH, 256>>>();
    k_actv<<<NB * HH, 256>>>(ssb);
    k_border<<<(NB * 512 * PD * PD + 255) / 256, 256>>>();
    k_atrans<<<dim3(PIX / 32, 512 / 32, NB), tb>>>();
    k_conv<<<dim3(4, 32, NB), 256>>>(sgb, sbb);
    k_final<<<NB * HH, 256>>>(x, cgb, cbb, bg, bb, out);
}